// round 10
// baseline (speedup 1.0000x reference)
#include <cuda_runtime.h>
#include <cstdint>

// PyramidROIAlign, warp-per-pool-point, geometry-mapped grid.
//   boxes: (2, 1000, 4) f32; p2: (2, 256, 256, 256) f32 NHWC
//   out:   (2, 1000, 7, 7, 256) f32
//
// KEY FACT (proved R6): for any normalized box h,w <= 1,
// clip(round(log2(sqrt(hw)/0.21875)),2,5) == 2 always -> only p2 sampled.
//
// Grid (2000, 7) x 224-thread CTAs (7 warps):
//   roi = blockIdx.x, py = blockIdx.y, px = warp id  -> ZERO divisions,
//   box load is the first instruction of the warp (no dep chain ahead).
//   98000 warps exact, no tail. 224thr x 32 regs -> 9 CTAs = 63 warps/SM.
//   A CTA's 7 warps sample one row py of one ROI -> shared (y0,y1) feature
//   rows -> maximal in-CTA L1 reuse.
// Per warp: 8 batched independent LDG.128 (4 corners x 2 channel halves),
// 2 lerps, 2 streaming STG.128.

#define BATCH   2
#define NROI    1000
#define POOLH   7
#define POOLW   7
#define NCH     256
#define NCH4    (NCH / 4)            // 64
#define POINTS  (POOLH * POOLW)      // 49
#define FH      256                  // p2 spatial size

__device__ __forceinline__ float4 lerp2(const float4 v00, const float4 v01,
                                        const float4 v10, const float4 v11,
                                        const float wx, const float wy)
{
    float4 r;
    float t, bo;
    t  = v00.x + wx * (v01.x - v00.x);
    bo = v10.x + wx * (v11.x - v10.x);
    r.x = t + wy * (bo - t);
    t  = v00.y + wx * (v01.y - v00.y);
    bo = v10.y + wx * (v11.y - v10.y);
    r.y = t + wy * (bo - t);
    t  = v00.z + wx * (v01.z - v00.z);
    bo = v10.z + wx * (v11.z - v10.z);
    r.z = t + wy * (bo - t);
    t  = v00.w + wx * (v01.w - v00.w);
    bo = v10.w + wx * (v11.w - v10.w);
    r.w = t + wy * (bo - t);
    return r;
}

__global__ __launch_bounds__(224, 9) void pyramid_roi_align_kernel(
    const float* __restrict__ boxes,
    const float* __restrict__ p2,
    float4* __restrict__ out)
{
    const int lane = threadIdx.x & 31;
    const int px   = threadIdx.x >> 5;     // warp id 0..6 = x sample
    const int roi  = blockIdx.x;           // 0..1999
    const int py   = blockIdx.y;           // 0..6

    // Box load FIRST — nothing ahead of it on the dependence chain.
    const float4 bx = __ldg((const float4*)(boxes) + roi);

    const int b = roi >= NROI ? 1 : 0;

    const float y1 = bx.x, x1 = bx.y, y2 = bx.z, x2 = bx.w;
    const float h = y2 - y1;
    const float w = x2 - x1;

    // level == 2 always (proof in header): sample p2, H = W = 256.
    const float Hm1 = (float)(FH - 1);
    const float ty = (float)py * (1.0f / 6.0f);
    const float tx = (float)px * (1.0f / 6.0f);
    const float ysf = (y1 + h * ty) * Hm1;
    const float xsf = (x1 + w * tx) * Hm1;

    const float y0f = floorf(ysf);
    const float x0f = floorf(xsf);
    const float wy = ysf - y0f;   // weights from UNCLAMPED floor (matches ref)
    const float wx = xsf - x0f;

    const int y0  = min(max((int)y0f, 0), FH - 1);
    const int y1i = min(max((int)y0f + 1, 0), FH - 1);
    const int x0  = min(max((int)x0f, 0), FH - 1);
    const int x1i = min(max((int)x0f + 1, 0), FH - 1);

    // NHWC float4 view: p2_4[((b*256 + y)*256 + x)*64 + c]
    const float4* __restrict__ f4 = (const float4*)p2;
    const int rowb0 = (b * FH + y0)  * FH;
    const int rowb1 = (b * FH + y1i) * FH;
    const float4* __restrict__ q00 = f4 + (rowb0 + x0 ) * NCH4 + lane;
    const float4* __restrict__ q01 = f4 + (rowb0 + x1i) * NCH4 + lane;
    const float4* __restrict__ q10 = f4 + (rowb1 + x0 ) * NCH4 + lane;
    const float4* __restrict__ q11 = f4 + (rowb1 + x1i) * NCH4 + lane;

    // ---- 8 batched independent gathers (channels lane, lane+32) ----
    const float4 a00 = __ldg(q00);
    const float4 a01 = __ldg(q01);
    const float4 a10 = __ldg(q10);
    const float4 a11 = __ldg(q11);
    const float4 b00 = __ldg(q00 + 32);
    const float4 b01 = __ldg(q01 + 32);
    const float4 b10 = __ldg(q10 + 32);
    const float4 b11 = __ldg(q11 + 32);

    const float4 ra = lerp2(a00, a01, a10, a11, wx, wy);
    const float4 rb = lerp2(b00, b01, b10, b11, wx, wy);

    // pt = roi*49 + py*7 + px ; out block = pt * 64 float4
    const int pt = (roi * POINTS) + py * POOLW + px;
    float4* __restrict__ o = out + (long long)pt * NCH4 + lane;
    __stcs(o,      ra);
    __stcs(o + 32, rb);
}

extern "C" void kernel_launch(void* const* d_in, const int* in_sizes, int n_in,
                              void* d_out, int out_size)
{
    const float* boxes = (const float*)d_in[0];
    const float* p2    = (const float*)d_in[1];
    float4* out = (float4*)d_out;

    dim3 grid(BATCH * NROI, POOLH);
    pyramid_roi_align_kernel<<<grid, POOLW * 32>>>(boxes, p2, out);
}

// round 11
// speedup vs baseline: 1.1977x; 1.1977x over previous
#include <cuda_runtime.h>
#include <cstdint>

// PyramidROIAlign: warp handles TWO pool points, all 16 gathers batched.
//   boxes: (2, 1000, 4) f32; p2: (2, 256, 256, 256) f32 NHWC
//   out:   (2, 1000, 7, 7, 256) f32
//
// KEY FACT (proved R6): for any normalized box h,w <= 1,
// clip(round(log2(sqrt(hw)/0.21875)),2,5) == 2 always -> only p2 sampled.
//
// R7 failed with a SERIAL per-point loop (loads behind compute). Here both
// points' 16 LDG.128 are issued back-to-back before any compute: one warp
// keeps the L1tex queue full 2x longer per scheduling turn, and the per-point
// prologue (divisions, box, clamps) is amortized across 2 points.
// 98000 points = 12250 blocks x 4 warps x 2 points, exact.

#define BATCH   2
#define NROI    1000
#define POOLH   7
#define POOLW   7
#define NCH     256
#define NCH4    (NCH / 4)            // 64
#define POINTS  (POOLH * POOLW)      // 49
#define NPTS    (BATCH * NROI * POINTS)   // 98000
#define FH      256                  // p2 spatial size

__device__ __forceinline__ float4 lerp2(const float4 v00, const float4 v01,
                                        const float4 v10, const float4 v11,
                                        const float wx, const float wy)
{
    float4 r;
    float t, bo;
    t  = v00.x + wx * (v01.x - v00.x);
    bo = v10.x + wx * (v11.x - v10.x);
    r.x = t + wy * (bo - t);
    t  = v00.y + wx * (v01.y - v00.y);
    bo = v10.y + wx * (v11.y - v10.y);
    r.y = t + wy * (bo - t);
    t  = v00.z + wx * (v01.z - v00.z);
    bo = v10.z + wx * (v11.z - v10.z);
    r.z = t + wy * (bo - t);
    t  = v00.w + wx * (v01.w - v00.w);
    bo = v10.w + wx * (v11.w - v10.w);
    r.w = t + wy * (bo - t);
    return r;
}

// Compute the four corner pointers + weights for one point.
__device__ __forceinline__ void point_setup(
    const float4 bx, int b, int py, int px, const float4* __restrict__ f4,
    int lane,
    const float4** q00, const float4** q01,
    const float4** q10, const float4** q11,
    float* owx, float* owy)
{
    const float y1 = bx.x, x1 = bx.y, y2 = bx.z, x2 = bx.w;
    const float h = y2 - y1;
    const float w = x2 - x1;

    const float Hm1 = (float)(FH - 1);
    const float ty = (float)py * (1.0f / 6.0f);
    const float tx = (float)px * (1.0f / 6.0f);
    const float ysf = (y1 + h * ty) * Hm1;
    const float xsf = (x1 + w * tx) * Hm1;

    const float y0f = floorf(ysf);
    const float x0f = floorf(xsf);
    *owy = ysf - y0f;   // weights from UNCLAMPED floor (matches ref)
    *owx = xsf - x0f;

    const int y0  = min(max((int)y0f, 0), FH - 1);
    const int y1i = min(max((int)y0f + 1, 0), FH - 1);
    const int x0  = min(max((int)x0f, 0), FH - 1);
    const int x1i = min(max((int)x0f + 1, 0), FH - 1);

    const int rowb0 = (b * FH + y0)  * FH;
    const int rowb1 = (b * FH + y1i) * FH;
    *q00 = f4 + (rowb0 + x0 ) * NCH4 + lane;
    *q01 = f4 + (rowb0 + x1i) * NCH4 + lane;
    *q10 = f4 + (rowb1 + x0 ) * NCH4 + lane;
    *q11 = f4 + (rowb1 + x1i) * NCH4 + lane;
}

__global__ __launch_bounds__(128, 6) void pyramid_roi_align_kernel(
    const float* __restrict__ boxes,
    const float* __restrict__ p2,
    float4* __restrict__ out)
{
    const int lane = threadIdx.x & 31;
    const int wrp  = threadIdx.x >> 5;
    const int W    = blockIdx.x * 4 + wrp;   // warp id 0..48999
    const int pt0  = W * 2;                  // first point (even)

    // Point 0 decomposition (magic div).
    const int roi0 = pt0 / POINTS;
    const int ppt0 = pt0 - roi0 * POINTS;    // 0..48
    // Point 1 = pt0 + 1 (branchless wrap).
    const int wrap = (ppt0 == POINTS - 1);
    const int roi1 = roi0 + wrap;
    const int ppt1 = wrap ? 0 : (ppt0 + 1);

    const int py0 = ppt0 / POOLW, px0 = ppt0 - py0 * POOLW;
    const int py1 = ppt1 / POOLW, px1 = ppt1 - py1 * POOLW;
    const int b0 = roi0 >= NROI ? 1 : 0;
    const int b1 = roi1 >= NROI ? 1 : 0;

    // Box loads (same address 48/49 of the time -> L1 hit).
    const float4 bx0 = __ldg((const float4*)(boxes) + roi0);
    const float4 bx1 = __ldg((const float4*)(boxes) + roi1);

    const float4* __restrict__ f4 = (const float4*)p2;

    const float4 *a_q00, *a_q01, *a_q10, *a_q11;
    const float4 *b_q00, *b_q01, *b_q10, *b_q11;
    float awx, awy, bwx, bwy;
    point_setup(bx0, b0, py0, px0, f4, lane, &a_q00, &a_q01, &a_q10, &a_q11, &awx, &awy);
    point_setup(bx1, b1, py1, px1, f4, lane, &b_q00, &b_q01, &b_q10, &b_q11, &bwx, &bwy);

    // ---- 16 batched independent gathers, issued back-to-back ----
    const float4 a00 = __ldg(a_q00);
    const float4 a01 = __ldg(a_q01);
    const float4 a10 = __ldg(a_q10);
    const float4 a11 = __ldg(a_q11);
    const float4 a00h = __ldg(a_q00 + 32);
    const float4 a01h = __ldg(a_q01 + 32);
    const float4 a10h = __ldg(a_q10 + 32);
    const float4 a11h = __ldg(a_q11 + 32);
    const float4 c00 = __ldg(b_q00);
    const float4 c01 = __ldg(b_q01);
    const float4 c10 = __ldg(b_q10);
    const float4 c11 = __ldg(b_q11);
    const float4 c00h = __ldg(b_q00 + 32);
    const float4 c01h = __ldg(b_q01 + 32);
    const float4 c10h = __ldg(b_q10 + 32);
    const float4 c11h = __ldg(b_q11 + 32);

    const float4 r0a = lerp2(a00,  a01,  a10,  a11,  awx, awy);
    const float4 r0b = lerp2(a00h, a01h, a10h, a11h, awx, awy);
    const float4 r1a = lerp2(c00,  c01,  c10,  c11,  bwx, bwy);
    const float4 r1b = lerp2(c00h, c01h, c10h, c11h, bwx, bwy);

    // Output: 2 consecutive points = 128 consecutive float4 (2KB).
    float4* __restrict__ o = out + (long long)pt0 * NCH4 + lane;
    __stcs(o,      r0a);
    __stcs(o + 32, r0b);
    __stcs(o + 64, r1a);
    __stcs(o + 96, r1b);
}

extern "C" void kernel_launch(void* const* d_in, const int* in_sizes, int n_in,
                              void* d_out, int out_size)
{
    const float* boxes = (const float*)d_in[0];
    const float* p2    = (const float*)d_in[1];
    float4* out = (float4*)d_out;

    pyramid_roi_align_kernel<<<NPTS / 8, 128>>>(boxes, p2, out);  // 12250 blocks
}

// round 12
// speedup vs baseline: 1.2589x; 1.0511x over previous
#include <cuda_runtime.h>
#include <cstdint>

// PyramidROIAlign, warp-per-pool-point (R9 structure, 64-thread CTAs).
//   boxes: (2, 1000, 4) f32; p2: (2, 256, 256, 256) f32 NHWC
//   out:   (2, 1000, 7, 7, 256) f32
//
// KEY FACT (proved R6): for any normalized box h,w <= 1,
// clip(round(log2(sqrt(hw)/0.21875)),2,5) == 2 always -> only p2 sampled.
//
// Session law (R4/R7/R8/R11): maximize (resident warps) x (batched loads
// per warp); 32 regs + 8 batched LDG.128 + 64 warps/SM is the optimum.
// R8->R9 (256->128 thr) showed finer CTA retire granularity helps; this
// round goes to 64-thr CTAs (32 CTAs/SM x 2 warps = 64 warps, exactly
// filling the 64K-reg RF at 32 regs/thread).
// 98000 points = 49000 blocks x 2 warps, exact.

#define BATCH   2
#define NROI    1000
#define POOLH   7
#define POOLW   7
#define NCH     256
#define NCH4    (NCH / 4)            // 64
#define POINTS  (POOLH * POOLW)      // 49
#define NPTS    (BATCH * NROI * POINTS)   // 98000
#define FH      256                  // p2 spatial size

__device__ __forceinline__ float4 lerp2(const float4 v00, const float4 v01,
                                        const float4 v10, const float4 v11,
                                        const float wx, const float wy)
{
    float4 r;
    float t, bo;
    t  = v00.x + wx * (v01.x - v00.x);
    bo = v10.x + wx * (v11.x - v10.x);
    r.x = t + wy * (bo - t);
    t  = v00.y + wx * (v01.y - v00.y);
    bo = v10.y + wx * (v11.y - v10.y);
    r.y = t + wy * (bo - t);
    t  = v00.z + wx * (v01.z - v00.z);
    bo = v10.z + wx * (v11.z - v10.z);
    r.z = t + wy * (bo - t);
    t  = v00.w + wx * (v01.w - v00.w);
    bo = v10.w + wx * (v11.w - v10.w);
    r.w = t + wy * (bo - t);
    return r;
}

__global__ __launch_bounds__(64, 32) void pyramid_roi_align_kernel(
    const float* __restrict__ boxes,
    const float* __restrict__ p2,
    float4* __restrict__ out)
{
    const int lane = threadIdx.x & 31;
    const int wrp  = threadIdx.x >> 5;
    const int pt   = blockIdx.x * 2 + wrp;    // 0..97999, exact

    // ---- warp-uniform param computation (registers only) ----
    const int roi = pt / POINTS;              // IMAD magic div
    const int ppt = pt - roi * POINTS;        // 0..48
    const int py  = ppt / POOLW;
    const int px  = ppt - py * POOLW;
    const int b   = roi >= NROI ? 1 : 0;

    const float4 bx = __ldg((const float4*)(boxes) + roi);
    const float y1 = bx.x, x1 = bx.y, y2 = bx.z, x2 = bx.w;
    const float h = y2 - y1;
    const float w = x2 - x1;

    // level == 2 always (proof in header): sample p2, H = W = 256.
    const float Hm1 = (float)(FH - 1);
    const float ty = (float)py * (1.0f / 6.0f);
    const float tx = (float)px * (1.0f / 6.0f);
    const float ysf = (y1 + h * ty) * Hm1;
    const float xsf = (x1 + w * tx) * Hm1;

    const float y0f = floorf(ysf);
    const float x0f = floorf(xsf);
    const float wy = ysf - y0f;   // weights from UNCLAMPED floor (matches ref)
    const float wx = xsf - x0f;

    const int y0  = min(max((int)y0f, 0), FH - 1);
    const int y1i = min(max((int)y0f + 1, 0), FH - 1);
    const int x0  = min(max((int)x0f, 0), FH - 1);
    const int x1i = min(max((int)x0f + 1, 0), FH - 1);

    // NHWC float4 view: p2_4[((b*256 + y)*256 + x)*64 + c]
    const float4* __restrict__ f4 = (const float4*)p2;
    const int rowb0 = (b * FH + y0)  * FH;
    const int rowb1 = (b * FH + y1i) * FH;
    const float4* __restrict__ q00 = f4 + (rowb0 + x0 ) * NCH4 + lane;
    const float4* __restrict__ q01 = f4 + (rowb0 + x1i) * NCH4 + lane;
    const float4* __restrict__ q10 = f4 + (rowb1 + x0 ) * NCH4 + lane;
    const float4* __restrict__ q11 = f4 + (rowb1 + x1i) * NCH4 + lane;

    // ---- 8 batched independent gathers (channels lane, lane+32) ----
    const float4 a00 = __ldg(q00);
    const float4 a01 = __ldg(q01);
    const float4 a10 = __ldg(q10);
    const float4 a11 = __ldg(q11);
    const float4 b00 = __ldg(q00 + 32);
    const float4 b01 = __ldg(q01 + 32);
    const float4 b10 = __ldg(q10 + 32);
    const float4 b11 = __ldg(q11 + 32);

    const float4 ra = lerp2(a00, a01, a10, a11, wx, wy);
    const float4 rb = lerp2(b00, b01, b10, b11, wx, wy);

    // out point block: pt * 64 float4
    float4* __restrict__ o = out + (long long)pt * NCH4 + lane;
    __stcs(o,      ra);
    __stcs(o + 32, rb);
}

extern "C" void kernel_launch(void* const* d_in, const int* in_sizes, int n_in,
                              void* d_out, int out_size)
{
    const float* boxes = (const float*)d_in[0];
    const float* p2    = (const float*)d_in[1];
    float4* out = (float4*)d_out;

    pyramid_roi_align_kernel<<<NPTS / 2, 64>>>(boxes, p2, out);  // 49000 blocks
}